// round 15
// baseline (speedup 1.0000x reference)
#include <cuda_runtime.h>

#define BB 8192
#define TT 256

// Scratch (no allocations allowed).
// x repacked as x4[t/4][b][4]: one float4 = 4 timesteps for one batch.
// One extra group for the branchless group prefetch (loaded, never consumed).
__device__ __align__(16) float g_x4[(TT / 4 + 1) * BB * 4];
// Quad2 layout, natural rows: 4 lanes per batch. Lane q: tp = q&1 (type-pair:
// 0 -> {i,f}, 1 -> {g,o}), hh = q>>1 (k-half). Lane owns 10 gates: cols
// c=0..9 with type = 2*tp + c/5, k = 5*hh + c%5. Rows j = 0..9 natural.
__device__ __align__(16) float g_w4[4 * 10 * 10];  // [q][j][c]
__device__ __align__(16) float g_wih4[4 * 10];     // [q][c]
__device__ __align__(16) float g_bb4[4 * 10];      // [q][c]

__device__ __forceinline__ float tanh_approx(float x) {
    float y; asm("tanh.approx.f32 %0, %1;" : "=f"(y) : "f"(x)); return y;
}

// ---------------------------------------------------------------------------
// Fused prep: every block transposes one 32x32 tile of x into the x4 layout;
// block (0,0) additionally samples the variational weights
// (w = mu + softplus(rho)*eps) into the Quad2 layout with the sigmoid
// half-angle pre-scale (sigmoid(z) = 0.5*tanh(z/2)+0.5):
//   types 0,1,3 (i,f,o): S = 0.5 ;  type 2 (g -> tanh): S = 1.0
// ---------------------------------------------------------------------------
__global__ void prep_kernel(const float* __restrict__ x,
                            const float* __restrict__ wih_mu, const float* __restrict__ wih_rho,
                            const float* __restrict__ whh_mu, const float* __restrict__ whh_rho,
                            const float* __restrict__ b_mu,   const float* __restrict__ b_rho,
                            const float* __restrict__ eps_ih, const float* __restrict__ eps_hh,
                            const float* __restrict__ eps_b)
{
    __shared__ float tile[32][33];
    int t0 = blockIdx.x * 32, b0 = blockIdx.y * 32;
    int tx = threadIdx.x, ty = threadIdx.y;
#pragma unroll
    for (int i = ty; i < 32; i += 8)
        tile[i][tx] = x[(size_t)(b0 + i) * TT + t0 + tx];
    __syncthreads();
#pragma unroll
    for (int i = ty; i < 32; i += 8) {
        int t = t0 + i;
        g_x4[(size_t)(t >> 2) * (BB * 4) + (size_t)(b0 + tx) * 4 + (t & 3)] = tile[tx][i];
    }

    if (blockIdx.x == 0 && blockIdx.y == 0) {
        int tid = ty * 32 + tx;  // 0..255
        for (int idx = tid; idx < 400; idx += 256) {
            int q = idx / 100, rem = idx % 100, j = rem / 10, c = rem % 10;
            int tp = q & 1, hh = (q >> 1) & 1;
            int type = 2 * tp + c / 5;
            int k = 5 * hh + c % 5;
            int gate = 10 * type + k;
            float S = (type == 2) ? 1.f : 0.5f;
            int wi = j * 40 + gate;
            float w = whh_mu[wi] + log1pf(expf(whh_rho[wi])) * eps_hh[wi];
            g_w4[q * 100 + j * 10 + c] = S * w;
        }
        if (tid < 40) {
            int q = tid / 10, c = tid % 10;
            int tp = q & 1, hh = (q >> 1) & 1;
            int type = 2 * tp + c / 5;
            int k = 5 * hh + c % 5;
            int gate = 10 * type + k;
            float S = (type == 2) ? 1.f : 0.5f;
            g_wih4[q * 10 + c] = S * (wih_mu[gate] + log1pf(expf(wih_rho[gate])) * eps_ih[gate]);
            g_bb4[q * 10 + c]  = S * (b_mu[gate]   + log1pf(expf(b_rho[gate]))   * eps_b[gate]);
        }
    }
}

// ---------------------------------------------------------------------------
// Main recurrence (Quad2, scalar FFMA, distributed c/h, 6-shuffle exchange).
// 4 lanes per batch, 8 batches per warp, 1024 warps. Lane q (tp = q&1,
// hh = q>>1) computes 10 gates = types {2tp, 2tp+1} for k in [5hh, 5hh+5).
// GEMM: 110 scalar FFMA over register-resident full h[10] (natural order).
// Act exchange: each lane consumes only 6 (tp0) / 4 (tp1) partner acts, and
// shfl_xor carries different data each direction, so 6 shuffles (with 6
// tp-SELs choosing what to send) replace the 10-value swap:
//   tp0 receives partner acts {0,2,4, 5,7,9} -> rx[0..5]
//   tp1 receives partner acts {1,3,6,8, *,*} -> rx[0..3] (rx[4:] garbage)
// c/h update for k = 5*hh + m owned by lane with parity(m) == tp (uniform
// 3-iteration loop; iteration 3 is never-consumed garbage on tp1 lanes).
// h redistributed with 10 constant-source width-4 shuffles.
// x: one LDG.128 per 4 timesteps, prefetched 1 group ahead (pad group).
// ---------------------------------------------------------------------------
__global__ void __launch_bounds__(32)
lstm_kernel(const float* __restrict__ lin_w, const float* __restrict__ lin_b,
            float* __restrict__ out)
{
    const unsigned FULL = 0xffffffffu;
    int lane = threadIdx.x;
    int q    = lane & 3;
    int tp   = q & 1;
    int batch = blockIdx.x * 8 + (lane >> 2);

    // One-time: this lane's weights into registers (scalar).
    float w[100], wih[10], bb[10];
    {
        const float* wp = g_w4 + q * 100;
#pragma unroll
        for (int i = 0; i < 100; i++) w[i] = wp[i];
#pragma unroll
        for (int k = 0; k < 10; k++) {
            wih[k] = g_wih4[q * 10 + k];
            bb[k]  = g_bb4[q * 10 + k];
        }
    }

    // act cols 0..4 (type 2tp): tp=0 -> sigmoid(0.5,0.5), tp=1 -> tanh(1,0)
    // act cols 5..9 (type 2tp+1): always sigmoid (f or o)
    float A_lo = tp ? 1.f : 0.5f;
    float D_lo = tp ? 0.f : 0.5f;

    float h[10], cc[3], hown[3];
#pragma unroll
    for (int j = 0; j < 10; j++) h[j] = 0.f;
#pragma unroll
    for (int i = 0; i < 3; i++) { cc[i] = 0.f; hown[i] = 0.f; }

    const float4* xp = reinterpret_cast<const float4*>(g_x4) + batch;
    float4 cur = xp[0];

#pragma unroll 1
    for (int t4 = 0; t4 < TT / 4; t4++) {
        float4 nxt = xp[(size_t)(t4 + 1) * BB];  // group prefetch (pad group at end)
        float xs[4] = { cur.x, cur.y, cur.z, cur.w };

#pragma unroll
        for (int s = 0; s < 4; s++) {
            float xv = xs[s];

            // gates: acc = S * (x*w_ih + b + h @ w_hh)
            float acc[10];
#pragma unroll
            for (int k = 0; k < 10; k++) acc[k] = fmaf(xv, wih[k], bb[k]);
#pragma unroll
            for (int j = 0; j < 10; j++) {
                float hj = h[j];
#pragma unroll
                for (int k = 0; k < 10; k++) acc[k] = fmaf(hj, w[j * 10 + k], acc[k]);
            }

            // activations: 1 MUFU tanh + 1 FMA per gate
            float act[10];
#pragma unroll
            for (int p = 0; p < 10; p++) {
                float Ap = (p < 5) ? A_lo : 0.5f;
                float Dp = (p < 5) ? D_lo : 0.5f;
                act[p] = fmaf(Ap, tanh_approx(acc[p]), Dp);
            }

            // 6-shuffle act exchange: send what the partner needs.
            //   partner of tp0 (a tp1 lane) needs {1,3,6,8,*,*}
            //   partner of tp1 (a tp0 lane) needs {0,2,4,5,7,9}
            float rx[6];
            {
                const int A0[6] = {0, 2, 4, 5, 7, 9};   // what tp0 receives / tp1 sends
                const int A1[6] = {1, 3, 6, 8, 1, 1};   // what tp1 receives / tp0 sends
#pragma unroll
                for (int jj = 0; jj < 6; jj++) {
                    float snd = tp ? act[A0[jj]] : act[A1[jj]];
                    rx[jj] = __shfl_xor_sync(FULL, snd, 1, 4);
                }
            }

            // distributed c/h update: this lane owns m = 2*i + tp (m < 5).
            // Iteration i=2 on tp1 lanes computes garbage that is never read.
#pragma unroll
            for (int i = 0; i < 3; i++) {
                const int m0 = 2 * i;
                const int m1 = (2 * i + 1 < 5) ? (2 * i + 1) : 4;  // clamp (garbage lane)
                float am = tp ? act[m1] : act[m0];   // own i-or-g act at owned m
                float rm = rx[i];                    // partner's act at owned m
                float fv = tp ? rx[2 + i]   : act[5 + m0];  // forget gate
                float ov = tp ? act[5 + m1] : rx[3 + i];    // output gate
                cc[i]   = fmaf(fv, cc[i], am * rm);  // i*g is tp-symmetric
                hown[i] = ov * tanh_approx(cc[i]);
            }

            // redistribute h: owner of k is quad lane ((k/5)<<1) | ((k%5)&1),
            // holding it as hown[(k%5)>>1]. Constant source per k.
#pragma unroll
            for (int k = 0; k < 10; k++) {
                const int srcq = ((k / 5) << 1) | ((k % 5) & 1);
                h[k] = __shfl_sync(FULL, hown[(k % 5) >> 1], srcq, 4);
            }
        }
        cur = nxt;
    }

    // linear head: natural order. All lanes compute; q==0 lane stores.
    float s = lin_b[0];
#pragma unroll
    for (int j = 0; j < 10; j++) s = fmaf(h[j], lin_w[j], s);
    if (q == 0) out[batch] = s;
}

extern "C" void kernel_launch(void* const* d_in, const int* in_sizes, int n_in,
                              void* d_out, int out_size)
{
    const float* x       = (const float*)d_in[0];
    const float* wih_mu  = (const float*)d_in[1];
    const float* wih_rho = (const float*)d_in[2];
    const float* whh_mu  = (const float*)d_in[3];
    const float* whh_rho = (const float*)d_in[4];
    const float* b_mu    = (const float*)d_in[5];
    const float* b_rho   = (const float*)d_in[6];
    const float* eps_ih  = (const float*)d_in[7];
    const float* eps_hh  = (const float*)d_in[8];
    const float* eps_b   = (const float*)d_in[9];
    const float* lin_w   = (const float*)d_in[10];
    const float* lin_b   = (const float*)d_in[11];
    float* out = (float*)d_out;

    prep_kernel<<<dim3(TT / 32, BB / 32), dim3(32, 8)>>>(
        x, wih_mu, wih_rho, whh_mu, whh_rho, b_mu, b_rho, eps_ih, eps_hh, eps_b);
    lstm_kernel<<<BB / 8, 32>>>(lin_w, lin_b, out);
}

// round 16
// speedup vs baseline: 1.1690x; 1.1690x over previous
#include <cuda_runtime.h>

#define BB 8192
#define TT 256

// Scratch (no allocations allowed).
// x repacked as x4[t/4][b][4]: one float4 = 4 timesteps for one batch.
// Two extra groups for the branchless 2-group prefetch: they are loaded into
// registers on the final iteration but never consumed, so they are left
// uninitialized (reading them is safe; the values are dead).
__device__ __align__(16) float g_x4[(TT / 4 + 2) * BB * 4];
// Quad2 layout, natural rows: 4 lanes per batch. Lane q: tp = q&1 (type-pair:
// 0 -> {i,f}, 1 -> {g,o}), hh = q>>1 (k-half). Lane owns 10 gates: cols
// c=0..9 with type = 2*tp + c/5, k = 5*hh + c%5. Rows j = 0..9 natural.
__device__ __align__(16) float g_w4[4 * 10 * 10];  // [q][j][c]
__device__ __align__(16) float g_wih4[4 * 10];     // [q][c]
__device__ __align__(16) float g_bb4[4 * 10];      // [q][c]

__device__ __forceinline__ float tanh_approx(float x) {
    float y; asm("tanh.approx.f32 %0, %1;" : "=f"(y) : "f"(x)); return y;
}

// ---------------------------------------------------------------------------
// Fused prep: every block transposes one 32x32 tile of x into the x4 layout;
// block (0,0) additionally samples the variational weights
// (w = mu + softplus(rho)*eps) into the Quad2 layout with the sigmoid
// half-angle pre-scale (sigmoid(z) = 0.5*tanh(z/2)+0.5):
//   types 0,1,3 (i,f,o): S = 0.5 ;  type 2 (g -> tanh): S = 1.0
// ---------------------------------------------------------------------------
__global__ void prep_kernel(const float* __restrict__ x,
                            const float* __restrict__ wih_mu, const float* __restrict__ wih_rho,
                            const float* __restrict__ whh_mu, const float* __restrict__ whh_rho,
                            const float* __restrict__ b_mu,   const float* __restrict__ b_rho,
                            const float* __restrict__ eps_ih, const float* __restrict__ eps_hh,
                            const float* __restrict__ eps_b)
{
    __shared__ float tile[32][33];
    int t0 = blockIdx.x * 32, b0 = blockIdx.y * 32;
    int tx = threadIdx.x, ty = threadIdx.y;
#pragma unroll
    for (int i = ty; i < 32; i += 8)
        tile[i][tx] = x[(size_t)(b0 + i) * TT + t0 + tx];
    __syncthreads();
#pragma unroll
    for (int i = ty; i < 32; i += 8) {
        int t = t0 + i;
        g_x4[(size_t)(t >> 2) * (BB * 4) + (size_t)(b0 + tx) * 4 + (t & 3)] = tile[tx][i];
    }

    if (blockIdx.x == 0 && blockIdx.y == 0) {
        int tid = ty * 32 + tx;  // 0..255
        for (int idx = tid; idx < 400; idx += 256) {
            int q = idx / 100, rem = idx % 100, j = rem / 10, c = rem % 10;
            int tp = q & 1, hh = (q >> 1) & 1;
            int type = 2 * tp + c / 5;
            int k = 5 * hh + c % 5;
            int gate = 10 * type + k;
            float S = (type == 2) ? 1.f : 0.5f;
            int wi = j * 40 + gate;
            float w = whh_mu[wi] + log1pf(expf(whh_rho[wi])) * eps_hh[wi];
            g_w4[q * 100 + j * 10 + c] = S * w;
        }
        if (tid < 40) {
            int q = tid / 10, c = tid % 10;
            int tp = q & 1, hh = (q >> 1) & 1;
            int type = 2 * tp + c / 5;
            int k = 5 * hh + c % 5;
            int gate = 10 * type + k;
            float S = (type == 2) ? 1.f : 0.5f;
            g_wih4[q * 10 + c] = S * (wih_mu[gate] + log1pf(expf(wih_rho[gate])) * eps_ih[gate]);
            g_bb4[q * 10 + c]  = S * (b_mu[gate]   + log1pf(expf(b_rho[gate]))   * eps_b[gate]);
        }
    }
}

// ---------------------------------------------------------------------------
// Main recurrence (Quad2, scalar FFMA, distributed c/h update, 8x unroll).
// 4 lanes per batch, 8 batches per warp, 1024 warps. Lane q (tp = q&1,
// hh = q>>1) computes 10 gates = types {2tp, 2tp+1} for k in [5hh, 5hh+5).
// GEMM: 110 scalar FFMA over register-resident full h[10] (natural order).
// Per step: 10 shfl_xor(1) swap acts with the partner type-pair lane; the
// c/h update for k = 5*hh + m is owned by the lane with parity(m) == tp
// (uniform 3-iteration loop; iteration 3 is never-consumed garbage on tp1
// lanes). i*g is tp-symmetric; f/o picked by tp-SELs. h is redistributed
// with 10 constant-source width-4 shuffles. x: two LDG.128 per 8 timesteps,
// prefetched one iteration ahead (uninitialized tail groups are dead loads).
// ---------------------------------------------------------------------------
__global__ void __launch_bounds__(32)
lstm_kernel(const float* __restrict__ lin_w, const float* __restrict__ lin_b,
            float* __restrict__ out)
{
    const unsigned FULL = 0xffffffffu;
    int lane = threadIdx.x;
    int q    = lane & 3;
    int tp   = q & 1;
    int batch = blockIdx.x * 8 + (lane >> 2);

    // One-time: this lane's weights into registers (scalar).
    float w[100], wih[10], bb[10];
    {
        const float* wp = g_w4 + q * 100;
#pragma unroll
        for (int i = 0; i < 100; i++) w[i] = wp[i];
#pragma unroll
        for (int k = 0; k < 10; k++) {
            wih[k] = g_wih4[q * 10 + k];
            bb[k]  = g_bb4[q * 10 + k];
        }
    }

    // act cols 0..4 (type 2tp): tp=0 -> sigmoid(0.5,0.5), tp=1 -> tanh(1,0)
    // act cols 5..9 (type 2tp+1): always sigmoid (f or o)
    float A_lo = tp ? 1.f : 0.5f;
    float D_lo = tp ? 0.f : 0.5f;

    float h[10], cc[3], hown[3];
#pragma unroll
    for (int j = 0; j < 10; j++) h[j] = 0.f;
#pragma unroll
    for (int i = 0; i < 3; i++) { cc[i] = 0.f; hown[i] = 0.f; }

    const float4* xp = reinterpret_cast<const float4*>(g_x4) + batch;
    float4 cur0 = xp[0];
    float4 cur1 = xp[BB];

#pragma unroll 1
    for (int t8 = 0; t8 < TT / 8; t8++) {
        // prefetch the next two groups (tail groups are dead loads)
        float4 nxt0 = xp[(size_t)(2 * t8 + 2) * BB];
        float4 nxt1 = xp[(size_t)(2 * t8 + 3) * BB];
        float xs[8] = { cur0.x, cur0.y, cur0.z, cur0.w,
                        cur1.x, cur1.y, cur1.z, cur1.w };

#pragma unroll
        for (int s = 0; s < 8; s++) {
            float xv = xs[s];

            // gates: acc = S * (x*w_ih + b + h @ w_hh)
            float acc[10];
#pragma unroll
            for (int k = 0; k < 10; k++) acc[k] = fmaf(xv, wih[k], bb[k]);
#pragma unroll
            for (int j = 0; j < 10; j++) {
                float hj = h[j];
#pragma unroll
                for (int k = 0; k < 10; k++) acc[k] = fmaf(hj, w[j * 10 + k], acc[k]);
            }

            // activations: 1 MUFU tanh + 1 FMA per gate
            float act[10];
#pragma unroll
            for (int p = 0; p < 10; p++) {
                float Ap = (p < 5) ? A_lo : 0.5f;
                float Dp = (p < 5) ? D_lo : 0.5f;
                act[p] = fmaf(Ap, tanh_approx(acc[p]), Dp);
            }

            // swap acts with partner lane (other type-pair, same k-half)
            float recv[10];
#pragma unroll
            for (int p = 0; p < 10; p++)
                recv[p] = __shfl_xor_sync(FULL, act[p], 1, 4);

            // distributed c/h update: this lane owns m = 2*i + tp (m < 5).
            // Iteration i=2 on tp1 lanes computes garbage that is never read.
#pragma unroll
            for (int i = 0; i < 3; i++) {
                const int m0 = 2 * i;
                const int m1 = (2 * i + 1 < 5) ? (2 * i + 1) : 4;  // clamp (garbage lane)
                float am = tp ? act[m1]      : act[m0];
                float rm = tp ? recv[m1]     : recv[m0];
                float a5 = tp ? act[5 + m1]  : act[5 + m0];
                float r5 = tp ? recv[5 + m1] : recv[5 + m0];
                float fv = tp ? r5 : a5;
                float ov = tp ? a5 : r5;
                cc[i]   = fmaf(fv, cc[i], am * rm);           // i*g is tp-symmetric
                hown[i] = ov * tanh_approx(cc[i]);
            }

            // redistribute h: owner of k is quad lane ((k/5)<<1) | ((k%5)&1),
            // holding it as hown[(k%5)>>1]. Constant source per k.
#pragma unroll
            for (int k = 0; k < 10; k++) {
                const int srcq = ((k / 5) << 1) | ((k % 5) & 1);
                h[k] = __shfl_sync(FULL, hown[(k % 5) >> 1], srcq, 4);
            }
        }
        cur0 = nxt0;
        cur1 = nxt1;
    }

    // linear head: natural order. All lanes compute; q==0 lane stores.
    float s = lin_b[0];
#pragma unroll
    for (int j = 0; j < 10; j++) s = fmaf(h[j], lin_w[j], s);
    if (q == 0) out[batch] = s;
}

extern "C" void kernel_launch(void* const* d_in, const int* in_sizes, int n_in,
                              void* d_out, int out_size)
{
    const float* x       = (const float*)d_in[0];
    const float* wih_mu  = (const float*)d_in[1];
    const float* wih_rho = (const float*)d_in[2];
    const float* whh_mu  = (const float*)d_in[3];
    const float* whh_rho = (const float*)d_in[4];
    const float* b_mu    = (const float*)d_in[5];
    const float* b_rho   = (const float*)d_in[6];
    const float* eps_ih  = (const float*)d_in[7];
    const float* eps_hh  = (const float*)d_in[8];
    const float* eps_b   = (const float*)d_in[9];
    const float* lin_w   = (const float*)d_in[10];
    const float* lin_b   = (const float*)d_in[11];
    float* out = (float*)d_out;

    prep_kernel<<<dim3(TT / 32, BB / 32), dim3(32, 8)>>>(
        x, wih_mu, wih_rho, whh_mu, whh_rho, b_mu, b_rho, eps_ih, eps_hh, eps_b);
    lstm_kernel<<<BB / 8, 32>>>(lin_w, lin_b, out);
}

// round 17
// speedup vs baseline: 1.1721x; 1.0026x over previous
#include <cuda_runtime.h>

#define BB 8192
#define TT 256

// Scratch (no allocations allowed).
// x repacked as x4[t/4][b][4]: one float4 = 4 timesteps for one batch.
// Two extra groups for the branchless 2-group prefetch: they are loaded into
// registers on the final iteration but never consumed, so they are left
// uninitialized (reading them is safe; the values are dead).
__device__ __align__(16) float g_x4[(TT / 4 + 2) * BB * 4];
// Quad2 layout, natural rows: 4 lanes per batch. Lane q: tp = q&1 (type-pair:
// 0 -> {i,f}, 1 -> {g,o}), hh = q>>1 (k-half). Lane owns 10 gates: cols
// c=0..9 with type = 2*tp + c/5, k = 5*hh + c%5. Rows j = 0..9 natural.
__device__ __align__(16) float g_w4[4 * 10 * 10];  // [q][j][c]
__device__ __align__(16) float g_wih4[4 * 10];     // [q][c]
__device__ __align__(16) float g_bb4[4 * 10];      // [q][c]

__device__ __forceinline__ float tanh_approx(float x) {
    float y; asm("tanh.approx.f32 %0, %1;" : "=f"(y) : "f"(x)); return y;
}

// ---------------------------------------------------------------------------
// Fused prep: every block transposes one 32x32 tile of x into the x4 layout;
// block (0,0) additionally samples the variational weights
// (w = mu + softplus(rho)*eps) into the Quad2 layout with the sigmoid
// half-angle pre-scale (sigmoid(z) = 0.5*tanh(z/2)+0.5):
//   types 0,1,3 (i,f,o): S = 0.5 ;  type 2 (g -> tanh): S = 1.0
// ---------------------------------------------------------------------------
__global__ void prep_kernel(const float* __restrict__ x,
                            const float* __restrict__ wih_mu, const float* __restrict__ wih_rho,
                            const float* __restrict__ whh_mu, const float* __restrict__ whh_rho,
                            const float* __restrict__ b_mu,   const float* __restrict__ b_rho,
                            const float* __restrict__ eps_ih, const float* __restrict__ eps_hh,
                            const float* __restrict__ eps_b)
{
    __shared__ float tile[32][33];
    int t0 = blockIdx.x * 32, b0 = blockIdx.y * 32;
    int tx = threadIdx.x, ty = threadIdx.y;
#pragma unroll
    for (int i = ty; i < 32; i += 8)
        tile[i][tx] = x[(size_t)(b0 + i) * TT + t0 + tx];
    __syncthreads();
#pragma unroll
    for (int i = ty; i < 32; i += 8) {
        int t = t0 + i;
        g_x4[(size_t)(t >> 2) * (BB * 4) + (size_t)(b0 + tx) * 4 + (t & 3)] = tile[tx][i];
    }

    if (blockIdx.x == 0 && blockIdx.y == 0) {
        int tid = ty * 32 + tx;  // 0..255
        for (int idx = tid; idx < 400; idx += 256) {
            int q = idx / 100, rem = idx % 100, j = rem / 10, c = rem % 10;
            int tp = q & 1, hh = (q >> 1) & 1;
            int type = 2 * tp + c / 5;
            int k = 5 * hh + c % 5;
            int gate = 10 * type + k;
            float S = (type == 2) ? 1.f : 0.5f;
            int wi = j * 40 + gate;
            float w = whh_mu[wi] + log1pf(expf(whh_rho[wi])) * eps_hh[wi];
            g_w4[q * 100 + j * 10 + c] = S * w;
        }
        if (tid < 40) {
            int q = tid / 10, c = tid % 10;
            int tp = q & 1, hh = (q >> 1) & 1;
            int type = 2 * tp + c / 5;
            int k = 5 * hh + c % 5;
            int gate = 10 * type + k;
            float S = (type == 2) ? 1.f : 0.5f;
            g_wih4[q * 10 + c] = S * (wih_mu[gate] + log1pf(expf(wih_rho[gate])) * eps_ih[gate]);
            g_bb4[q * 10 + c]  = S * (b_mu[gate]   + log1pf(expf(b_rho[gate]))   * eps_b[gate]);
        }
    }
}

// ---------------------------------------------------------------------------
// Main recurrence (Quad2, scalar FFMA, distributed c/h update, 8x unroll).
// 4 lanes per batch, 8 batches per warp, 1024 warps. Lane q (tp = q&1,
// hh = q>>1) computes 10 gates = types {2tp, 2tp+1} for k in [5hh, 5hh+5).
// GEMM: 110 scalar FFMA over register-resident full h[10] (natural order).
// Per step: 10 shfl_xor(1) swap acts with the partner type-pair lane; the
// c/h update for k = 5*hh + m is owned by the lane with parity(m) == tp
// (uniform 3-iteration loop; iteration 3 is never-consumed garbage on tp1
// lanes). i*g is tp-symmetric; f/o picked by tp-SELs. h is redistributed
// with 10 constant-source width-4 shuffles. x: two LDG.128 per 8 timesteps,
// prefetched one iteration ahead (uninitialized tail groups are dead loads).
// ---------------------------------------------------------------------------
__global__ void __launch_bounds__(32)
lstm_kernel(const float* __restrict__ lin_w, const float* __restrict__ lin_b,
            float* __restrict__ out)
{
    const unsigned FULL = 0xffffffffu;
    int lane = threadIdx.x;
    int q    = lane & 3;
    int tp   = q & 1;
    int batch = blockIdx.x * 8 + (lane >> 2);

    // One-time: this lane's weights into registers (scalar).
    float w[100], wih[10], bb[10];
    {
        const float* wp = g_w4 + q * 100;
#pragma unroll
        for (int i = 0; i < 100; i++) w[i] = wp[i];
#pragma unroll
        for (int k = 0; k < 10; k++) {
            wih[k] = g_wih4[q * 10 + k];
            bb[k]  = g_bb4[q * 10 + k];
        }
    }

    // act cols 0..4 (type 2tp): tp=0 -> sigmoid(0.5,0.5), tp=1 -> tanh(1,0)
    // act cols 5..9 (type 2tp+1): always sigmoid (f or o)
    float A_lo = tp ? 1.f : 0.5f;
    float D_lo = tp ? 0.f : 0.5f;

    float h[10], cc[3], hown[3];
#pragma unroll
    for (int j = 0; j < 10; j++) h[j] = 0.f;
#pragma unroll
    for (int i = 0; i < 3; i++) { cc[i] = 0.f; hown[i] = 0.f; }

    const float4* xp = reinterpret_cast<const float4*>(g_x4) + batch;
    float4 cur0 = xp[0];
    float4 cur1 = xp[BB];

#pragma unroll 1
    for (int t8 = 0; t8 < TT / 8; t8++) {
        // prefetch the next two groups (tail groups are dead loads)
        float4 nxt0 = xp[(size_t)(2 * t8 + 2) * BB];
        float4 nxt1 = xp[(size_t)(2 * t8 + 3) * BB];
        float xs[8] = { cur0.x, cur0.y, cur0.z, cur0.w,
                        cur1.x, cur1.y, cur1.z, cur1.w };

#pragma unroll
        for (int s = 0; s < 8; s++) {
            float xv = xs[s];

            // gates: acc = S * (x*w_ih + b + h @ w_hh)
            float acc[10];
#pragma unroll
            for (int k = 0; k < 10; k++) acc[k] = fmaf(xv, wih[k], bb[k]);
#pragma unroll
            for (int j = 0; j < 10; j++) {
                float hj = h[j];
#pragma unroll
                for (int k = 0; k < 10; k++) acc[k] = fmaf(hj, w[j * 10 + k], acc[k]);
            }

            // activations: 1 MUFU tanh + 1 FMA per gate
            float act[10];
#pragma unroll
            for (int p = 0; p < 10; p++) {
                float Ap = (p < 5) ? A_lo : 0.5f;
                float Dp = (p < 5) ? D_lo : 0.5f;
                act[p] = fmaf(Ap, tanh_approx(acc[p]), Dp);
            }

            // swap acts with partner lane (other type-pair, same k-half)
            float recv[10];
#pragma unroll
            for (int p = 0; p < 10; p++)
                recv[p] = __shfl_xor_sync(FULL, act[p], 1, 4);

            // distributed c/h update: this lane owns m = 2*i + tp (m < 5).
            // Iteration i=2 on tp1 lanes computes garbage that is never read.
#pragma unroll
            for (int i = 0; i < 3; i++) {
                const int m0 = 2 * i;
                const int m1 = (2 * i + 1 < 5) ? (2 * i + 1) : 4;  // clamp (garbage lane)
                float am = tp ? act[m1]      : act[m0];
                float rm = tp ? recv[m1]     : recv[m0];
                float a5 = tp ? act[5 + m1]  : act[5 + m0];
                float r5 = tp ? recv[5 + m1] : recv[5 + m0];
                float fv = tp ? r5 : a5;
                float ov = tp ? a5 : r5;
                cc[i]   = fmaf(fv, cc[i], am * rm);           // i*g is tp-symmetric
                hown[i] = ov * tanh_approx(cc[i]);
            }

            // redistribute h: owner of k is quad lane ((k/5)<<1) | ((k%5)&1),
            // holding it as hown[(k%5)>>1]. Constant source per k.
#pragma unroll
            for (int k = 0; k < 10; k++) {
                const int srcq = ((k / 5) << 1) | ((k % 5) & 1);
                h[k] = __shfl_sync(FULL, hown[(k % 5) >> 1], srcq, 4);
            }
        }
        cur0 = nxt0;
        cur1 = nxt1;
    }

    // linear head: natural order. All lanes compute; q==0 lane stores.
    float s = lin_b[0];
#pragma unroll
    for (int j = 0; j < 10; j++) s = fmaf(h[j], lin_w[j], s);
    if (q == 0) out[batch] = s;
}

extern "C" void kernel_launch(void* const* d_in, const int* in_sizes, int n_in,
                              void* d_out, int out_size)
{
    const float* x       = (const float*)d_in[0];
    const float* wih_mu  = (const float*)d_in[1];
    const float* wih_rho = (const float*)d_in[2];
    const float* whh_mu  = (const float*)d_in[3];
    const float* whh_rho = (const float*)d_in[4];
    const float* b_mu    = (const float*)d_in[5];
    const float* b_rho   = (const float*)d_in[6];
    const float* eps_ih  = (const float*)d_in[7];
    const float* eps_hh  = (const float*)d_in[8];
    const float* eps_b   = (const float*)d_in[9];
    const float* lin_w   = (const float*)d_in[10];
    const float* lin_b   = (const float*)d_in[11];
    float* out = (float*)d_out;

    prep_kernel<<<dim3(TT / 32, BB / 32), dim3(32, 8)>>>(
        x, wih_mu, wih_rho, whh_mu, whh_rho, b_mu, b_rho, eps_ih, eps_hh, eps_b);
    lstm_kernel<<<BB / 8, 32>>>(lin_w, lin_b, out);
}